// round 17
// baseline (speedup 1.0000x reference)
#include <cuda_runtime.h>

// AudioOnlySpecAugment — persistent-CTA fused kernel.
// X: (B=32, T=2048, D=1536) f32. First 256 dims pass through; last A=1280 are audio.
// out[b,t,d] = X[b,t,d] (d<256); 0 if tmask[b,t] | fmask[b,d-256]; else X[b,t,d].
//
// Grid of 1216 persistent blocks (~8/SM). Each block's prologue computes ALL 32
// batches' mask params once (thread b -> batch b, coalesced scalar loads, one
// __syncthreads) into 512 B of shared, then grid-strides over rows reading
// params via conflict-free broadcast LDS. Per-row param overhead: ~8 instrs
// instead of ~110 -> issue/LSU slots go back to the 805 MB stream.

#define BATCH   32
#define SEQ_T   2048
#define DIM     1536
#define AUD     1280
#define VDIM    256
#define F4_PER_ROW (DIM / 4)   // 384
#define THREADS 128
#define N_ROWS  (BATCH * SEQ_T)   // 65536
#define GRID    1216              // ~8 blocks/SM on 148-152 SMs, single wave

__global__ void __launch_bounds__(THREADS, 8)
spec_aug_persistent_kernel(const float4* __restrict__ X,
                           const int*    __restrict__ len_raw,  // int32 or int64, sniffed
                           const float*  __restrict__ u_t,
                           const float*  __restrict__ u_t0,
                           const float*  __restrict__ u_f,
                           const float*  __restrict__ u_f0,
                           float4*       __restrict__ out)
{
    // sp[2b] = {t0_0, tend_0, t0_1, tend_1}; sp[2b+1] = {f0_0, fend_0, f0_1, fend_1}
    __shared__ int4 sp[BATCH * 2];

    // ---- Prologue: 32 threads compute 32 batches' params in parallel ----
    if (threadIdx.x < 32) {
        const int b = threadIdx.x;

        // dtype sniff on the first 128 bytes (valid under both layouts):
        // int64 storage -> all 16 odd int32 words are 0 (values < 2^32).
        // int32 storage -> random lengths; all-zero ~ 2048^-16.
        const int odd = __ldg(len_raw + 2 * (b & 15) + 1);
        const bool is_i64 = (__ballot_sync(0xFFFFFFFFu, odd == 0) == 0xFFFFFFFFu);
        const int len = is_i64 ? __ldg(len_raw + 2 * b) : __ldg(len_raw + b);

        // --- time masks (TR = 0.2), exact f32 reference semantics ---
        const float max_t = floorf((float)len * 0.2f);
        const int tn0  = (int)floorf(__ldg(u_t + b) * (max_t + 1.0f));
        const int rem0 = len - tn0;
        const int t00  = (rem0 <= 0) ? 0
                       : (int)floorf(__ldg(u_t0 + b) * ((float)rem0 + 1.0f));
        const int tn1  = (int)floorf(__ldg(u_t + BATCH + b) * (max_t + 1.0f));
        const int rem1 = len - tn1;
        const int t10  = (rem1 <= 0) ? 0
                       : (int)floorf(__ldg(u_t0 + BATCH + b) * ((float)rem1 + 1.0f));

        // --- freq masks: max_f = int(1280 * double(0.15)) = 192 -> mult 193.0f ---
        const int fa   = (int)floorf(__ldg(u_f + b) * 193.0f);
        int f0mA = AUD - fa; if (f0mA < 0) f0mA = 0;
        const int f00  = (int)floorf(__ldg(u_f0 + b) * ((float)f0mA + 1.0f));
        const int fb   = (int)floorf(__ldg(u_f + BATCH + b) * 193.0f);
        int f0mB = AUD - fb; if (f0mB < 0) f0mB = 0;
        const int f10  = (int)floorf(__ldg(u_f0 + BATCH + b) * ((float)f0mB + 1.0f));

        sp[2 * b]     = make_int4(t00, t00 + tn0, t10, t10 + tn1);
        sp[2 * b + 1] = make_int4(f00, f00 + fa,  f10, f10 + fb);
    }
    __syncthreads();

    // ---- Grid-stride streaming loop: consecutive blocks -> consecutive rows ----
    for (int row = blockIdx.x; row < N_ROWS; row += GRID) {
        const int b = row >> 11;            // T = 2048
        const int t = row & (SEQ_T - 1);

        const float4* src = X   + (size_t)row * F4_PER_ROW;
        float4*       dst = out + (size_t)row * F4_PER_ROW;

        // Front-batch the streaming loads (evict-first: touched exactly once).
        float4 v0 = __ldcs(src + threadIdx.x);
        float4 v1 = __ldcs(src + threadIdx.x + THREADS);
        float4 v2 = __ldcs(src + threadIdx.x + 2 * THREADS);

        // Broadcast LDS (conflict-free), hidden behind the loads above.
        const int4 tp = sp[2 * b];
        const int4 fq = sp[2 * b + 1];
        const bool tm = (t >= tp.x && t < tp.y) || (t >= tp.z && t < tp.w);

        float4 v[3] = {v0, v1, v2};
        #pragma unroll
        for (int i = 0; i < 3; i++) {
            const int c4 = threadIdx.x + i * THREADS;   // 0..383
            const int d  = c4 * 4;
            if (d >= VDIM) {                            // audio region
                if (tm) {
                    v[i].x = 0.0f; v[i].y = 0.0f; v[i].z = 0.0f; v[i].w = 0.0f;
                } else {
                    const int a = d - VDIM;
                    if ((a     >= fq.x && a     < fq.y) || (a     >= fq.z && a     < fq.w)) v[i].x = 0.0f;
                    if ((a + 1 >= fq.x && a + 1 < fq.y) || (a + 1 >= fq.z && a + 1 < fq.w)) v[i].y = 0.0f;
                    if ((a + 2 >= fq.x && a + 2 < fq.y) || (a + 2 >= fq.z && a + 2 < fq.w)) v[i].z = 0.0f;
                    if ((a + 3 >= fq.x && a + 3 < fq.y) || (a + 3 >= fq.z && a + 3 < fq.w)) v[i].w = 0.0f;
                }
            }
            __stcs(dst + c4, v[i]);   // evict-first store: output never re-read
        }
    }
}

extern "C" void kernel_launch(void* const* d_in, const int* in_sizes, int n_in,
                              void* d_out, int out_size)
{
    const float4* X    = (const float4*)d_in[0];
    const int*    lenr = (const int*)d_in[1];      // int32 OR int64 — sniffed on device
    const float*  u_t  = (const float*)d_in[2];
    const float*  u_t0 = (const float*)d_in[3];
    const float*  u_f  = (const float*)d_in[4];
    const float*  u_f0 = (const float*)d_in[5];
    float4*       out  = (float4*)d_out;

    spec_aug_persistent_kernel<<<GRID, THREADS>>>(X, lenr, u_t, u_t0, u_f, u_f0, out);
}